// round 1
// baseline (speedup 1.0000x reference)
#include <cuda_runtime.h>

// CrossAttentionConditionInjection — analytic collapse.
//
// K/V come from a single condition token broadcast across seq, so every
// attention score row is constant => softmax weights are exactly 1/S
// (S=2048 is a power of two) => attn == v1 broadcast. The entire op is:
//   out[b,s,:] = Wo @ (Wv @ cond[b] + bv) + bo   for all s.

#define BDIM 1024   // D
#define NB   2      // B
#define NS   2048   // S

__device__ float g_v1[NB * BDIM];
__device__ float g_o1[NB * BDIM];

// ---------------------------------------------------------------------------
// Warp-per-row matvec: y[b*D + d] = dot(W[d,:], x[b,:]) + bias[d]
// Stage 1: x = condition (from d_in), y = g_v1
// Stage 2: x = g_v1,                  y = g_o1
// ---------------------------------------------------------------------------
__global__ void mv_stage1(const float* __restrict__ Wv,
                          const float* __restrict__ cond,
                          const float* __restrict__ bv) {
    int w    = (blockIdx.x * blockDim.x + threadIdx.x) >> 5;   // 0..2047
    int lane = threadIdx.x & 31;
    if (w >= NB * BDIM) return;
    int b = w >> 10;
    int d = w & (BDIM - 1);

    const float4* Wr = reinterpret_cast<const float4*>(Wv + (size_t)d * BDIM);
    const float4* xr = reinterpret_cast<const float4*>(cond + (size_t)b * BDIM);

    float sum = 0.f;
#pragma unroll
    for (int i = 0; i < BDIM / 128; ++i) {          // 8 iterations of float4
        float4 wv = Wr[lane + i * 32];
        float4 xv = xr[lane + i * 32];
        sum += wv.x * xv.x + wv.y * xv.y + wv.z * xv.z + wv.w * xv.w;
    }
#pragma unroll
    for (int off = 16; off; off >>= 1)
        sum += __shfl_xor_sync(0xffffffffu, sum, off);
    if (lane == 0) g_v1[w] = sum + bv[d];
}

__global__ void mv_stage2(const float* __restrict__ Wo,
                          const float* __restrict__ bo) {
    int w    = (blockIdx.x * blockDim.x + threadIdx.x) >> 5;
    int lane = threadIdx.x & 31;
    if (w >= NB * BDIM) return;
    int b = w >> 10;
    int d = w & (BDIM - 1);

    const float4* Wr = reinterpret_cast<const float4*>(Wo + (size_t)d * BDIM);
    const float4* xr = reinterpret_cast<const float4*>(g_v1 + (size_t)b * BDIM);

    float sum = 0.f;
#pragma unroll
    for (int i = 0; i < BDIM / 128; ++i) {
        float4 wv = Wr[lane + i * 32];
        float4 xv = xr[lane + i * 32];
        sum += wv.x * xv.x + wv.y * xv.y + wv.z * xv.z + wv.w * xv.w;
    }
#pragma unroll
    for (int off = 16; off; off >>= 1)
        sum += __shfl_xor_sync(0xffffffffu, sum, off);
    if (lane == 0) g_o1[w] = sum + bo[d];
}

// ---------------------------------------------------------------------------
// Broadcast: out[b,s,d] = g_o1[b,d] for all s. Pure coalesced float4 stores;
// g_o1 (8 KB) lives in L1/L2 after first touch. One float4 store per thread.
// Total float4 elements = B*S*D/4 = 1,048,576 (S*D/4 = 2^19, D/4 = 256).
// ---------------------------------------------------------------------------
__global__ void bcast_kernel(float4* __restrict__ out) {
    const float4* o1 = reinterpret_cast<const float4*>(g_o1);
    int i  = blockIdx.x * blockDim.x + threadIdx.x;
    int b  = i >> 19;          // / (S*D/4)
    int d4 = i & 255;          // % (D/4)
    out[i] = o1[(b << 8) + d4];
}

extern "C" void kernel_launch(void* const* d_in, const int* in_sizes, int n_in,
                              void* d_out, int out_size) {
    // metadata order: hidden_states, condition, Wq, bq, Wk, bk, Wv, bv, Wo, bo
    const float* cond = (const float*)d_in[1];
    const float* Wv   = (const float*)d_in[6];
    const float* bv   = (const float*)d_in[7];
    const float* Wo   = (const float*)d_in[8];
    const float* bo   = (const float*)d_in[9];
    float*       out  = (float*)d_out;

    // 2048 output rows per stage, warp per row, 8 warps/block -> 256 blocks
    mv_stage1<<<256, 256>>>(Wv, cond, bv);
    mv_stage2<<<256, 256>>>(Wo, bo);

    // 1,048,576 float4 stores: 2048 blocks x 512 threads, one store each
    bcast_kernel<<<(NB * NS * BDIM / 4) / 512, 512>>>((float4*)out);
}